// round 8
// baseline (speedup 1.0000x reference)
#include <cuda_runtime.h>
#include <math.h>
#include <stdint.h>

// Problem dims
#define BB 32
#define TT 256
#define VV 32000
#define HH 512
#define G3 1536          // 3*H
#define NROW (BB*TT)     // 8192

// ---------------- packed f32x2 helpers (sm_103a) ----------------
#define FMA2(d, a, b, c) asm("fma.rn.f32x2 %0, %1, %2, %3;" : "=l"(d) : "l"(a), "l"(b), "l"(c))
#define PACK2(d, lo, hi) asm("mov.b64 %0, {%1, %2};" : "=l"(d) : "f"(lo), "f"(hi))
#define UNPACK2(lo, hi, s) asm("mov.b64 {%0, %1}, %2;" : "=f"(lo), "=f"(hi) : "l"(s))

// ---------------- device scratch (no allocations allowed) ----------------
__device__ float g_gi0T[(size_t)G3 * NROW];    // [1536][8192] precomputed input gates layer0 (+bih0)
__device__ float g_outsT[(size_t)HH * NROW];   // [512][8192]  h2 outputs, k-major for GEMM2
__device__ float g_h[HH * BB];                 // packed pair layout: (k>>1)*64 + b*2 + (k&1)
__device__ float g_h1[HH * BB];
__device__ float g_W1rz[1024 * HH];            // Wih1+Whh1 rows 0..1023 (r,z gates)
__device__ float g_b1rz[1024];
__device__ unsigned g_bar;

__device__ __forceinline__ float sigmoidf_(float x) { return 1.f / (1.f + __expf(-x)); }

// ---------------- prep: combined layer-1 weights, zero h, reset barrier ----------------
__global__ void prep_kernel(const float* __restrict__ Wih1, const float* __restrict__ Whh1,
                            const float* __restrict__ bih1, const float* __restrict__ bhh1)
{
    int i = blockIdx.x * blockDim.x + threadIdx.x;
    int stride = gridDim.x * blockDim.x;
    for (int idx = i; idx < 1024 * HH; idx += stride)
        g_W1rz[idx] = Wih1[idx] + Whh1[idx];
    if (i < 1024) g_b1rz[i] = bih1[i] + bhh1[i];
    for (int idx = i; idx < HH * BB; idx += stride) g_h[idx] = 0.f;
    if (i == 0) g_bar = 0u;
}

// ---------------- generic fp32 GEMM, f32x2 inner, 128x128x16 tiles ----------------
// C[m][n] = sum_k A(m,k) * B(n,k) + bias
// A_KMAJOR: A stored [K][M] (lda = M); else row-major [M][K]
// GATHER_B: B row n comes from emb[x[b*T+t]] with n = t*32+b
// REMAP_OUT: C index = ((m&31)*TT + (m>>5))*N + n   (row r = t*32+b -> [b][t][v])
template<bool A_KMAJOR, bool BIAS_M, bool GATHER_B, bool REMAP_OUT>
__global__ void __launch_bounds__(256, 2) gemm_f32(
    const float* __restrict__ A, const float* __restrict__ Bm,
    const float* __restrict__ bias, float* __restrict__ C,
    int M, int N, int K,
    const int* __restrict__ xidx, const float* __restrict__ emb)
{
    __shared__ float As[16][128];
    __shared__ float Bs[16][128];
    const int bm = blockIdx.y * 128;
    const int bn = blockIdx.x * 128;
    const int tid = threadIdx.x;
    const int tx = tid & 15, ty = tid >> 4;

    unsigned long long acc[8][4];
#pragma unroll
    for (int i = 0; i < 8; i++)
#pragma unroll
        for (int j = 0; j < 4; j++) acc[i][j] = 0ull;

    for (int k0 = 0; k0 < K; k0 += 16) {
#pragma unroll
        for (int p = 0; p < 2; p++) {
            int e = tid + p * 256;  // float4 index, 512 per tile
            // ---- A tile ----
            if (A_KMAJOR) {
                int kk = e >> 5; int mq = (e & 31) << 2;
                float4 v = *(const float4*)(A + (size_t)(k0 + kk) * M + bm + mq);
                *(float4*)(&As[kk][mq]) = v;
            } else {
                int row = e >> 2; int kq = (e & 3) << 2;
                float4 v = *(const float4*)(A + (size_t)(bm + row) * K + k0 + kq);
                As[kq + 0][row] = v.x; As[kq + 1][row] = v.y;
                As[kq + 2][row] = v.z; As[kq + 3][row] = v.w;
            }
            // ---- B tile (always [n][k] rows) ----
            {
                int row = e >> 2; int kq = (e & 3) << 2;
                const float* src;
                if (GATHER_B) {
                    int n = bn + row;
                    int bb2 = n & 31, t2 = n >> 5;
                    int xi = __ldg(&xidx[bb2 * TT + t2]);
                    src = emb + (size_t)xi * K + k0 + kq;
                } else {
                    src = Bm + (size_t)(bn + row) * K + k0 + kq;
                }
                float4 v = *(const float4*)src;
                Bs[kq + 0][row] = v.x; Bs[kq + 1][row] = v.y;
                Bs[kq + 2][row] = v.z; Bs[kq + 3][row] = v.w;
            }
        }
        __syncthreads();
#pragma unroll
        for (int kk = 0; kk < 16; kk++) {
            float a[8];
            // b operands are contiguous pairs in smem: reinterpret the loaded
            // float4 register quads as aligned 64-bit pairs (no pack MOVs).
            union { float4 f4[2]; unsigned long long u2[4]; } bu;
            *(float4*)a       = *(const float4*)(&As[kk][ty * 8]);
            *(float4*)(a + 4) = *(const float4*)(&As[kk][ty * 8 + 4]);
            bu.f4[0] = *(const float4*)(&Bs[kk][tx * 8]);
            bu.f4[1] = *(const float4*)(&Bs[kk][tx * 8 + 4]);
#pragma unroll
            for (int i = 0; i < 8; i++) {
                unsigned long long a2;
                PACK2(a2, a[i], a[i]);
#pragma unroll
                for (int j = 0; j < 4; j++) FMA2(acc[i][j], a2, bu.u2[j], acc[i][j]);
            }
        }
        __syncthreads();
    }

#pragma unroll
    for (int i = 0; i < 8; i++) {
        int m = bm + ty * 8 + i;
        size_t rowoff;
        if (REMAP_OUT) rowoff = ((size_t)(m & 31) * TT + (size_t)(m >> 5)) * (size_t)N;
        else           rowoff = (size_t)m * (size_t)N;
        float biasm = BIAS_M ? bias[m] : 0.f;
#pragma unroll
        for (int j = 0; j < 4; j++) {
            float lo, hi;
            UNPACK2(lo, hi, acc[i][j]);
            int n0 = bn + tx * 8 + 2 * j;
            if (BIAS_M) { lo += biasm; hi += biasm; }
            else        { lo += bias[n0]; hi += bias[n0 + 1]; }
            float2 v2 = make_float2(lo, hi);
            *(float2*)(C + rowoff + n0) = v2;
        }
    }
}

// ---------------- persistent recurrent kernel ----------------
// 128 CTAs x 256 threads. CTA owns hidden dims j = cta*4 .. cta*4+3.
// warps: jj = w&3, kh = w>>2 (k-half split with smem reduction).
#define RNC 128
#define SMEM_FLOATS (16384 + 6144 + 8192 + 1024)

__device__ __forceinline__ void gbarrier(unsigned target)
{
    __syncthreads();
    if (threadIdx.x == 0) {
        __threadfence();
        atomicAdd(&g_bar, 1u);
        unsigned v;
        do {
            asm volatile("ld.global.acquire.gpu.u32 %0, [%1];" : "=r"(v) : "l"(&g_bar) : "memory");
        } while (v < target);
    }
    __syncthreads();
}

__global__ void __launch_bounds__(256, 1) recurrent_kernel(
    const float* __restrict__ Whh0, const float* __restrict__ bhh0,
    const float* __restrict__ Wih1n, const float* __restrict__ bih1n,
    const float* __restrict__ Whh1n, const float* __restrict__ bhh1n)
{
    extern __shared__ float sm[];
    float* hs  = sm;            // 16384 (h in packed pair layout)
    float* w0s = sm + 16384;    // [12][512]: (gate g=0..2)*4 + jj
    float* w1s = w0s + 6144;    // [16][512]: g=0:r  g=1:z  g=2:inn  g=3:hn
    float* red = w1s + 8192;    // 512 float2

    const int tid = threadIdx.x;
    const int cta = blockIdx.x;
    const int b = tid & 31;
    const int w = tid >> 5;
    const int jj = w & 3;
    const int kh = w >> 2;
    const int j = cta * 4 + jj;

    // ---- stage weights into SMEM (once) ----
    for (int idx = tid; idx < 12 * 512; idx += 256) {
        int row = idx >> 9, k = idx & 511;
        int g = row >> 2, jj2 = row & 3;
        w0s[idx] = Whh0[((size_t)(g * 512 + cta * 4 + jj2)) * 512 + k];
    }
    for (int idx = tid; idx < 16 * 512; idx += 256) {
        int row = idx >> 9, k = idx & 511;
        int g = row >> 2, jj2 = row & 3;
        int jq = cta * 4 + jj2;
        const float* src = (g == 0) ? &g_W1rz[(size_t)jq * 512]
                          : (g == 1) ? &g_W1rz[(size_t)(512 + jq) * 512]
                          : (g == 2) ? &Wih1n[(size_t)jq * 512]
                                     : &Whh1n[(size_t)jq * 512];
        w1s[idx] = src[k];
    }
    // biases (used by kh==0 threads only)
    const float br0 = bhh0[j], bz0 = bhh0[512 + j], bn0 = bhh0[1024 + j];
    const float b1r = g_b1rz[j], b1z = g_b1rz[512 + j];
    const float bi1n = bih1n[j], bh1n = bhh1n[j];
    __syncthreads();

    const int hidx = (j >> 1) * 64 + b * 2 + (j & 1);  // packed-pair index for (b, j)
    unsigned target = 0;

    for (int t = 0; t < TT; t++) {
        // ===== phase A: layer 0 =====
        for (int idx = tid * 4; idx < HH * BB; idx += 1024) {
            float4 v = __ldcg((const float4*)(g_h + idx));
            *(float4*)(hs + idx) = v;
        }
        __syncthreads();
        {
            unsigned long long ar = 0ull, az = 0ull, an = 0ull;
            const unsigned long long* wr2 = (const unsigned long long*)(w0s + (0 * 4 + jj) * 512 + kh * 256);
            const unsigned long long* wz2 = (const unsigned long long*)(w0s + (4 + jj) * 512 + kh * 256);
            const unsigned long long* wn2 = (const unsigned long long*)(w0s + (8 + jj) * 512 + kh * 256);
            const unsigned long long* hp  = (const unsigned long long*)hs + (size_t)kh * 128 * 32 + b;
#pragma unroll 8
            for (int k2 = 0; k2 < 128; k2++) {
                unsigned long long hv = hp[(size_t)k2 * 32];
                FMA2(ar, hv, wr2[k2], ar);
                FMA2(az, hv, wz2[k2], az);
                FMA2(an, hv, wn2[k2], an);
            }
            if (kh) {
                *(unsigned long long*)&red[((0 * 4 + jj) * 32 + b) * 2] = ar;
                *(unsigned long long*)&red[((4 + jj) * 32 + b) * 2]     = az;
                *(unsigned long long*)&red[((8 + jj) * 32 + b) * 2]     = an;
            }
            __syncthreads();
            if (!kh) {
                float arx, ary, azx, azy, anx, any_;
                UNPACK2(arx, ary, ar); UNPACK2(azx, azy, az); UNPACK2(anx, any_, an);
                float2 rr = *(float2*)&red[((0 * 4 + jj) * 32 + b) * 2];
                float2 rz = *(float2*)&red[((4 + jj) * 32 + b) * 2];
                float2 rn = *(float2*)&red[((8 + jj) * 32 + b) * 2];
                float sr = arx + ary + rr.x + rr.y;
                float sz = azx + azy + rz.x + rz.y;
                float sn = anx + any_ + rn.x + rn.y;
                size_t r0 = (size_t)t * 32 + b;
                float ir  = __ldg(&g_gi0T[(size_t)j * NROW + r0]);
                float iz  = __ldg(&g_gi0T[(size_t)(512 + j) * NROW + r0]);
                float inn = __ldg(&g_gi0T[(size_t)(1024 + j) * NROW + r0]);
                float rg = sigmoidf_(ir + sr + br0);
                float zg = sigmoidf_(iz + sz + bz0);
                float ng = tanhf(inn + rg * (sn + bn0));
                float hprev = hs[hidx];
                g_h1[hidx] = (1.f - zg) * ng + zg * hprev;
            }
        }
        target += RNC; gbarrier(target);

        // ===== phase B: layer 1 (x == h == h1) =====
        for (int idx = tid * 4; idx < HH * BB; idx += 1024) {
            float4 v = __ldcg((const float4*)(g_h1 + idx));
            *(float4*)(hs + idx) = v;
        }
        __syncthreads();
        {
            unsigned long long ar = 0ull, az = 0ull, ai = 0ull, ah = 0ull;
            const unsigned long long* wr2 = (const unsigned long long*)(w1s + (0 * 4 + jj) * 512 + kh * 256);
            const unsigned long long* wz2 = (const unsigned long long*)(w1s + (4 + jj) * 512 + kh * 256);
            const unsigned long long* wi2 = (const unsigned long long*)(w1s + (8 + jj) * 512 + kh * 256);
            const unsigned long long* wh2 = (const unsigned long long*)(w1s + (12 + jj) * 512 + kh * 256);
            const unsigned long long* hp  = (const unsigned long long*)hs + (size_t)kh * 128 * 32 + b;
#pragma unroll 8
            for (int k2 = 0; k2 < 128; k2++) {
                unsigned long long hv = hp[(size_t)k2 * 32];
                FMA2(ar, hv, wr2[k2], ar);
                FMA2(az, hv, wz2[k2], az);
                FMA2(ai, hv, wi2[k2], ai);
                FMA2(ah, hv, wh2[k2], ah);
            }
            if (kh) {
                *(unsigned long long*)&red[((0 * 4 + jj) * 32 + b) * 2]  = ar;
                *(unsigned long long*)&red[((4 + jj) * 32 + b) * 2]      = az;
                *(unsigned long long*)&red[((8 + jj) * 32 + b) * 2]      = ai;
                *(unsigned long long*)&red[((12 + jj) * 32 + b) * 2]     = ah;
            }
            __syncthreads();
            if (!kh) {
                float x0, x1;
                float sr, sz, si, sh;
                UNPACK2(x0, x1, ar); { float2 rv = *(float2*)&red[((0 * 4 + jj) * 32 + b) * 2]; sr = x0 + x1 + rv.x + rv.y; }
                UNPACK2(x0, x1, az); { float2 rv = *(float2*)&red[((4 + jj) * 32 + b) * 2];     sz = x0 + x1 + rv.x + rv.y; }
                UNPACK2(x0, x1, ai); { float2 rv = *(float2*)&red[((8 + jj) * 32 + b) * 2];     si = x0 + x1 + rv.x + rv.y; }
                UNPACK2(x0, x1, ah); { float2 rv = *(float2*)&red[((12 + jj) * 32 + b) * 2];    sh = x0 + x1 + rv.x + rv.y; }
                float rg = sigmoidf_(sr + b1r);
                float zg = sigmoidf_(sz + b1z);
                float ng = tanhf((si + bi1n) + rg * (sh + bh1n));
                float h1v = hs[hidx];
                float h2 = (1.f - zg) * ng + zg * h1v;
                g_h[hidx] = h2;
                g_outsT[(size_t)j * NROW + (size_t)t * 32 + b] = h2;
            }
        }
        target += RNC; gbarrier(target);
    }
}

// ---------------- launch ----------------
extern "C" void kernel_launch(void* const* d_in, const int* in_sizes, int n_in,
                              void* d_out, int out_size)
{
    const int*   x    = (const int*)d_in[0];
    const float* emb  = (const float*)d_in[1];
    const float* Wih  = (const float*)d_in[2];   // [2][1536][512]
    const float* Whh  = (const float*)d_in[3];
    const float* bih  = (const float*)d_in[4];   // [2][1536]
    const float* bhh  = (const float*)d_in[5];
    const float* Wout = (const float*)d_in[6];   // [32000][512]
    const float* bout = (const float*)d_in[7];
    float* out = (float*)d_out;

    const size_t L1W = (size_t)G3 * HH;          // layer-1 weight offset
    const size_t NOFF = L1W + (size_t)1024 * HH; // n-gate rows of layer 1

    prep_kernel<<<256, 256>>>(Wih + L1W, Whh + L1W, bih + G3, bhh + G3);

    float* gi0T;  cudaGetSymbolAddress((void**)&gi0T,  g_gi0T);
    float* outsT; cudaGetSymbolAddress((void**)&outsT, g_outsT);

    // gi0T[1536][8192] = Wih0 @ E^T + bih0 (embedding gather fused into B load)
    gemm_f32<false, true, true, false><<<dim3(NROW / 128, G3 / 128), 256>>>(
        Wih, nullptr, bih, gi0T, G3, NROW, HH, x, emb);

    cudaFuncSetAttribute(recurrent_kernel,
                         cudaFuncAttributeMaxDynamicSharedMemorySize, SMEM_FLOATS * 4);
    recurrent_kernel<<<RNC, 256, SMEM_FLOATS * 4>>>(
        Whh, bhh, Wih + NOFF, bih + G3 + 1024, Whh + NOFF, bhh + G3 + 1024);

    // logits[b][t][v] = outsT^T @ Wout^T + bout
    gemm_f32<true, false, false, true><<<dim3(VV / 128, NROW / 128), 256>>>(
        outsT, Wout, bout, out, NROW, VV, HH, nullptr, nullptr);
}

// round 16
// speedup vs baseline: 1.7031x; 1.7031x over previous
#include <cuda_runtime.h>
#include <cuda_bf16.h>
#include <math.h>
#include <stdint.h>

// Problem dims
#define BB 32
#define TT 256
#define VV 32000
#define HH 512
#define G3 1536          // 3*H
#define NROW (BB*TT)     // 8192

// ---------------- packed f32x2 helpers (sm_103a) ----------------
#define FMA2(d, a, b, c) asm("fma.rn.f32x2 %0, %1, %2, %3;" : "=l"(d) : "l"(a), "l"(b), "l"(c))
#define PACK2(d, lo, hi) asm("mov.b64 %0, {%1, %2};" : "=l"(d) : "f"(lo), "f"(hi))
#define UNPACK2(lo, hi, s) asm("mov.b64 {%0, %1}, %2;" : "=f"(lo), "=f"(hi) : "l"(s))

// ---------------- tensor-core helpers (mma.sync bf16) ----------------
#define LDSM4T(r, addr) asm volatile( \
    "ldmatrix.sync.aligned.m8n8.x4.trans.shared.b16 {%0,%1,%2,%3}, [%4];" \
    : "=r"((r)[0]), "=r"((r)[1]), "=r"((r)[2]), "=r"((r)[3]) : "r"(addr))
#define LDSM4(r, addr) asm volatile( \
    "ldmatrix.sync.aligned.m8n8.x4.shared.b16 {%0,%1,%2,%3}, [%4];" \
    : "=r"((r)[0]), "=r"((r)[1]), "=r"((r)[2]), "=r"((r)[3]) : "r"(addr))
#define MMA_BF16(c, a, b0, b1) asm volatile( \
    "mma.sync.aligned.m16n8k16.row.col.f32.bf16.bf16.f32 " \
    "{%0,%1,%2,%3}, {%4,%5,%6,%7}, {%8,%9}, {%0,%1,%2,%3};" \
    : "+f"((c)[0]), "+f"((c)[1]), "+f"((c)[2]), "+f"((c)[3]) \
    : "r"((a)[0]), "r"((a)[1]), "r"((a)[2]), "r"((a)[3]), "r"(b0), "r"(b1))

__device__ __forceinline__ uint32_t smem_u32(const void* p) {
    uint32_t a;
    asm("{ .reg .u64 t; cvta.to.shared.u64 t, %1; cvt.u32.u64 %0, t; }" : "=r"(a) : "l"(p));
    return a;
}

// split fp32 pair into bf16 hi pair + bf16 lo (residual) pair
__device__ __forceinline__ void cvt_pair(float x, float y, uint32_t& hi, uint32_t& lo) {
    __nv_bfloat162 h = __floats2bfloat162_rn(x, y);
    float rx = x - __low2float(h);
    float ry = y - __high2float(h);
    __nv_bfloat162 l2 = __floats2bfloat162_rn(rx, ry);
    hi = *(uint32_t*)&h;
    lo = *(uint32_t*)&l2;
}

// ---------------- device scratch (no allocations allowed) ----------------
__device__ float g_gi0T[(size_t)G3 * NROW];    // [1536][8192] precomputed input gates layer0 (+bih0)
__device__ float g_outsT[(size_t)HH * NROW];   // [512][8192]  h2 outputs, k-major for GEMM2
__device__ float g_h[HH * BB];                 // packed pair layout: (k>>1)*64 + b*2 + (k&1)
__device__ float g_h1[HH * BB];
__device__ float g_W1rz[1024 * HH];            // Wih1+Whh1 rows 0..1023 (r,z gates)
__device__ float g_b1rz[1024];
__device__ unsigned g_bar;

__device__ __forceinline__ float sigmoidf_(float x) { return 1.f / (1.f + __expf(-x)); }

// ---------------- prep: combined layer-1 weights, zero h, reset barrier ----------------
__global__ void prep_kernel(const float* __restrict__ Wih1, const float* __restrict__ Whh1,
                            const float* __restrict__ bih1, const float* __restrict__ bhh1)
{
    int i = blockIdx.x * blockDim.x + threadIdx.x;
    int stride = gridDim.x * blockDim.x;
    for (int idx = i; idx < 1024 * HH; idx += stride)
        g_W1rz[idx] = Wih1[idx] + Whh1[idx];
    if (i < 1024) g_b1rz[i] = bih1[i] + bhh1[i];
    for (int idx = i; idx < HH * BB; idx += stride) g_h[idx] = 0.f;
    if (i == 0) g_bar = 0u;
}

// ---------------- generic fp32 GEMM (used for input-gate GEMM only) ----------------
template<bool A_KMAJOR, bool BIAS_M, bool GATHER_B, bool REMAP_OUT>
__global__ void __launch_bounds__(256, 2) gemm_f32(
    const float* __restrict__ A, const float* __restrict__ Bm,
    const float* __restrict__ bias, float* __restrict__ C,
    int M, int N, int K,
    const int* __restrict__ xidx, const float* __restrict__ emb)
{
    __shared__ float As[16][128];
    __shared__ float Bs[16][128];
    const int bm = blockIdx.y * 128;
    const int bn = blockIdx.x * 128;
    const int tid = threadIdx.x;
    const int tx = tid & 15, ty = tid >> 4;

    unsigned long long acc[8][4];
#pragma unroll
    for (int i = 0; i < 8; i++)
#pragma unroll
        for (int j = 0; j < 4; j++) acc[i][j] = 0ull;

    for (int k0 = 0; k0 < K; k0 += 16) {
#pragma unroll
        for (int p = 0; p < 2; p++) {
            int e = tid + p * 256;
            if (A_KMAJOR) {
                int kk = e >> 5; int mq = (e & 31) << 2;
                float4 v = *(const float4*)(A + (size_t)(k0 + kk) * M + bm + mq);
                *(float4*)(&As[kk][mq]) = v;
            } else {
                int row = e >> 2; int kq = (e & 3) << 2;
                float4 v = *(const float4*)(A + (size_t)(bm + row) * K + k0 + kq);
                As[kq + 0][row] = v.x; As[kq + 1][row] = v.y;
                As[kq + 2][row] = v.z; As[kq + 3][row] = v.w;
            }
            {
                int row = e >> 2; int kq = (e & 3) << 2;
                const float* src;
                if (GATHER_B) {
                    int n = bn + row;
                    int bb2 = n & 31, t2 = n >> 5;
                    int xi = __ldg(&xidx[bb2 * TT + t2]);
                    src = emb + (size_t)xi * K + k0 + kq;
                } else {
                    src = Bm + (size_t)(bn + row) * K + k0 + kq;
                }
                float4 v = *(const float4*)src;
                Bs[kq + 0][row] = v.x; Bs[kq + 1][row] = v.y;
                Bs[kq + 2][row] = v.z; Bs[kq + 3][row] = v.w;
            }
        }
        __syncthreads();
#pragma unroll
        for (int kk = 0; kk < 16; kk++) {
            float a[8];
            union { float4 f4[2]; unsigned long long u2[4]; } bu;
            *(float4*)a       = *(const float4*)(&As[kk][ty * 8]);
            *(float4*)(a + 4) = *(const float4*)(&As[kk][ty * 8 + 4]);
            bu.f4[0] = *(const float4*)(&Bs[kk][tx * 8]);
            bu.f4[1] = *(const float4*)(&Bs[kk][tx * 8 + 4]);
#pragma unroll
            for (int i = 0; i < 8; i++) {
                unsigned long long a2;
                PACK2(a2, a[i], a[i]);
#pragma unroll
                for (int j = 0; j < 4; j++) FMA2(acc[i][j], a2, bu.u2[j], acc[i][j]);
            }
        }
        __syncthreads();
    }

#pragma unroll
    for (int i = 0; i < 8; i++) {
        int m = bm + ty * 8 + i;
        size_t rowoff;
        if (REMAP_OUT) rowoff = ((size_t)(m & 31) * TT + (size_t)(m >> 5)) * (size_t)N;
        else           rowoff = (size_t)m * (size_t)N;
        float biasm = BIAS_M ? bias[m] : 0.f;
#pragma unroll
        for (int j = 0; j < 4; j++) {
            float lo, hi;
            UNPACK2(lo, hi, acc[i][j]);
            int n0 = bn + tx * 8 + 2 * j;
            if (BIAS_M) { lo += biasm; hi += biasm; }
            else        { lo += bias[n0]; hi += bias[n0 + 1]; }
            float2 v2 = make_float2(lo, hi);
            *(float2*)(C + rowoff + n0) = v2;
        }
    }
}

// ---------------- output GEMM: bf16 split-3 tensor-core (mma.sync m16n8k16) ----------------
// C[b][t][v] = sum_k outsT[k][m] * Wout[v][k] + bout[v],  m = t*32+b
// A (outsT) k-major in gmem. Tile BM=128, BN=128, BK=64. 8 warps (2x4), warp tile 64x32.
// fp32 -> bf16 hi/lo split; acc += Ah*Bh + Ah*Bl + Al*Bh  (3 mma terms, fp32 accum).
#define A_STR 136   // b16 row stride for A smem [64 k][128 m + pad 8]
#define B_STR 72    // b16 row stride for B smem [128 n][64 k + pad 8]
#define G2_SMEM ((64*A_STR*2 + 128*B_STR*2) * 2)   // 71680 bytes

__global__ void __launch_bounds__(256, 2) gemm2_bf16(
    const float* __restrict__ A, const float* __restrict__ Bm,
    const float* __restrict__ bias, float* __restrict__ C)
{
    extern __shared__ char sm2[];
    uint32_t* Ah32 = (uint32_t*)sm2;                       // A_hi: 64*136 b16
    uint32_t* Al32 = Ah32 + (64 * A_STR) / 2;              // A_lo
    uint32_t* Bh32 = Al32 + (64 * A_STR) / 2;              // B_hi: 128*72 b16
    uint32_t* Bl32 = Bh32 + (128 * B_STR) / 2;             // B_lo

    const uint32_t ah_u = smem_u32(Ah32);
    const uint32_t al_u = smem_u32(Al32);
    const uint32_t bh_u = smem_u32(Bh32);
    const uint32_t bl_u = smem_u32(Bl32);

    const int tid = threadIdx.x;
    const int w = tid >> 5, l = tid & 31;
    const int wm = w >> 2, wn = w & 3;                      // 2 x 4 warp grid
    const int bn = blockIdx.x * 128, bm = blockIdx.y * 128;

    float acc[16][4];                                       // [mt*4+nt][c0..c3]
#pragma unroll
    for (int i = 0; i < 16; i++)
#pragma unroll
        for (int j = 0; j < 4; j++) acc[i][j] = 0.f;

    // per-lane ldmatrix address components (mat = l>>3)
    const int mat = l >> 3;
    const int r8  = l & 7;
    const int a_koff = (mat >> 1) * 8 + r8;                 // k row within 16x16 A tile
    const int a_moff = (mat & 1) * 8;                       // m col offset
    const int b_noff = (mat >> 1) * 8 + r8;                 // n row within 16x16 B block
    const int b_koff = (mat & 1) * 8;                       // k col offset

    for (int s = 0; s < 8; s++) {
        const int k0 = s * 64;
        // ---- load + convert A tile: [64 k][128 m], gmem k-major ----
#pragma unroll
        for (int i = 0; i < 8; i++) {
            int idx = tid + i * 256;                        // 2048 float4
            int kl = idx >> 5, m4 = (idx & 31) << 2;
            float4 v = __ldg((const float4*)(A + (size_t)(k0 + kl) * NROW + bm + m4));
            uint32_t h01, l01, h23, l23;
            cvt_pair(v.x, v.y, h01, l01);
            cvt_pair(v.z, v.w, h23, l23);
            int o = kl * (A_STR / 2) + (m4 >> 1);
            Ah32[o] = h01; Ah32[o + 1] = h23;
            Al32[o] = l01; Al32[o + 1] = l23;
        }
        // ---- load + convert B tile: [128 n][64 k], gmem n-major ----
#pragma unroll
        for (int i = 0; i < 8; i++) {
            int idx = tid + i * 256;
            int nl = idx >> 4, k4 = (idx & 15) << 2;
            float4 v = __ldg((const float4*)(Bm + (size_t)(bn + nl) * HH + k0 + k4));
            uint32_t h01, l01, h23, l23;
            cvt_pair(v.x, v.y, h01, l01);
            cvt_pair(v.z, v.w, h23, l23);
            int o = nl * (B_STR / 2) + (k4 >> 1);
            Bh32[o] = h01; Bh32[o + 1] = h23;
            Bl32[o] = l01; Bl32[o + 1] = l23;
        }
        __syncthreads();

#pragma unroll
        for (int ks = 0; ks < 4; ks++) {
            // A fragments for all 4 m-tiles (hi and lo)
            uint32_t a_h[4][4], a_l[4][4];
#pragma unroll
            for (int mt = 0; mt < 4; mt++) {
                uint32_t off = (uint32_t)((ks * 16 + a_koff) * A_STR
                                          + wm * 64 + mt * 16 + a_moff) * 2;
                LDSM4T(a_h[mt], ah_u + off);
                LDSM4T(a_l[mt], al_u + off);
            }
#pragma unroll
            for (int p = 0; p < 2; p++) {                   // two n-tile pairs
                uint32_t b_h[4], b_l[4];
                uint32_t off = (uint32_t)((wn * 32 + p * 16 + b_noff) * B_STR
                                          + ks * 16 + b_koff) * 2;
                LDSM4(b_h, bh_u + off);
                LDSM4(b_l, bl_u + off);
#pragma unroll
                for (int q = 0; q < 2; q++) {
                    int nt = p * 2 + q;
#pragma unroll
                    for (int mt = 0; mt < 4; mt++) {
                        MMA_BF16(acc[mt * 4 + nt], a_h[mt], b_h[2 * q], b_h[2 * q + 1]);
                        MMA_BF16(acc[mt * 4 + nt], a_h[mt], b_l[2 * q], b_l[2 * q + 1]);
                        MMA_BF16(acc[mt * 4 + nt], a_l[mt], b_h[2 * q], b_h[2 * q + 1]);
                    }
                }
            }
        }
        __syncthreads();
    }

    // ---- epilogue: bias + remap [m=t*32+b] -> [b][t][v] ----
#pragma unroll
    for (int mt = 0; mt < 4; mt++) {
#pragma unroll
        for (int nt = 0; nt < 4; nt++) {
            float* c = acc[mt * 4 + nt];
            int m1 = bm + wm * 64 + mt * 16 + (l >> 2);
            int m2 = m1 + 8;
            int n0 = bn + wn * 32 + nt * 8 + ((l & 3) << 1);
            float b0 = __ldg(&bias[n0]), b1 = __ldg(&bias[n0 + 1]);
            size_t r1 = ((size_t)(m1 & 31) * TT + (size_t)(m1 >> 5)) * (size_t)VV;
            size_t r2 = ((size_t)(m2 & 31) * TT + (size_t)(m2 >> 5)) * (size_t)VV;
            *(float2*)(C + r1 + n0) = make_float2(c[0] + b0, c[1] + b1);
            *(float2*)(C + r2 + n0) = make_float2(c[2] + b0, c[3] + b1);
        }
    }
}

// ---------------- persistent recurrent kernel (unchanged) ----------------
#define RNC 128
#define SMEM_FLOATS (16384 + 6144 + 8192 + 1024)

__device__ __forceinline__ void gbarrier(unsigned target)
{
    __syncthreads();
    if (threadIdx.x == 0) {
        __threadfence();
        atomicAdd(&g_bar, 1u);
        unsigned v;
        do {
            asm volatile("ld.global.acquire.gpu.u32 %0, [%1];" : "=r"(v) : "l"(&g_bar) : "memory");
        } while (v < target);
    }
    __syncthreads();
}

__global__ void __launch_bounds__(256, 1) recurrent_kernel(
    const float* __restrict__ Whh0, const float* __restrict__ bhh0,
    const float* __restrict__ Wih1n, const float* __restrict__ bih1n,
    const float* __restrict__ Whh1n, const float* __restrict__ bhh1n)
{
    extern __shared__ float sm[];
    float* hs  = sm;
    float* w0s = sm + 16384;
    float* w1s = w0s + 6144;
    float* red = w1s + 8192;

    const int tid = threadIdx.x;
    const int cta = blockIdx.x;
    const int b = tid & 31;
    const int w = tid >> 5;
    const int jj = w & 3;
    const int kh = w >> 2;
    const int j = cta * 4 + jj;

    for (int idx = tid; idx < 12 * 512; idx += 256) {
        int row = idx >> 9, k = idx & 511;
        int g = row >> 2, jj2 = row & 3;
        w0s[idx] = Whh0[((size_t)(g * 512 + cta * 4 + jj2)) * 512 + k];
    }
    for (int idx = tid; idx < 16 * 512; idx += 256) {
        int row = idx >> 9, k = idx & 511;
        int g = row >> 2, jj2 = row & 3;
        int jq = cta * 4 + jj2;
        const float* src = (g == 0) ? &g_W1rz[(size_t)jq * 512]
                          : (g == 1) ? &g_W1rz[(size_t)(512 + jq) * 512]
                          : (g == 2) ? &Wih1n[(size_t)jq * 512]
                                     : &Whh1n[(size_t)jq * 512];
        w1s[idx] = src[k];
    }
    const float br0 = bhh0[j], bz0 = bhh0[512 + j], bn0 = bhh0[1024 + j];
    const float b1r = g_b1rz[j], b1z = g_b1rz[512 + j];
    const float bi1n = bih1n[j], bh1n = bhh1n[j];
    __syncthreads();

    const int hidx = (j >> 1) * 64 + b * 2 + (j & 1);
    unsigned target = 0;

    for (int t = 0; t < TT; t++) {
        for (int idx = tid * 4; idx < HH * BB; idx += 1024) {
            float4 v = __ldcg((const float4*)(g_h + idx));
            *(float4*)(hs + idx) = v;
        }
        __syncthreads();
        {
            unsigned long long ar = 0ull, az = 0ull, an = 0ull;
            const unsigned long long* wr2 = (const unsigned long long*)(w0s + (0 * 4 + jj) * 512 + kh * 256);
            const unsigned long long* wz2 = (const unsigned long long*)(w0s + (4 + jj) * 512 + kh * 256);
            const unsigned long long* wn2 = (const unsigned long long*)(w0s + (8 + jj) * 512 + kh * 256);
            const unsigned long long* hp  = (const unsigned long long*)hs + (size_t)kh * 128 * 32 + b;
#pragma unroll 8
            for (int k2 = 0; k2 < 128; k2++) {
                unsigned long long hv = hp[(size_t)k2 * 32];
                FMA2(ar, hv, wr2[k2], ar);
                FMA2(az, hv, wz2[k2], az);
                FMA2(an, hv, wn2[k2], an);
            }
            if (kh) {
                *(unsigned long long*)&red[((0 * 4 + jj) * 32 + b) * 2] = ar;
                *(unsigned long long*)&red[((4 + jj) * 32 + b) * 2]     = az;
                *(unsigned long long*)&red[((8 + jj) * 32 + b) * 2]     = an;
            }
            __syncthreads();
            if (!kh) {
                float arx, ary, azx, azy, anx, any_;
                UNPACK2(arx, ary, ar); UNPACK2(azx, azy, az); UNPACK2(anx, any_, an);
                float2 rr = *(float2*)&red[((0 * 4 + jj) * 32 + b) * 2];
                float2 rz = *(float2*)&red[((4 + jj) * 32 + b) * 2];
                float2 rn = *(float2*)&red[((8 + jj) * 32 + b) * 2];
                float sr = arx + ary + rr.x + rr.y;
                float sz = azx + azy + rz.x + rz.y;
                float sn = anx + any_ + rn.x + rn.y;
                size_t r0 = (size_t)t * 32 + b;
                float ir  = __ldg(&g_gi0T[(size_t)j * NROW + r0]);
                float iz  = __ldg(&g_gi0T[(size_t)(512 + j) * NROW + r0]);
                float inn = __ldg(&g_gi0T[(size_t)(1024 + j) * NROW + r0]);
                float rg = sigmoidf_(ir + sr + br0);
                float zg = sigmoidf_(iz + sz + bz0);
                float ng = tanhf(inn + rg * (sn + bn0));
                float hprev = hs[hidx];
                g_h1[hidx] = (1.f - zg) * ng + zg * hprev;
            }
        }
        target += RNC; gbarrier(target);

        for (int idx = tid * 4; idx < HH * BB; idx += 1024) {
            float4 v = __ldcg((const float4*)(g_h1 + idx));
            *(float4*)(hs + idx) = v;
        }
        __syncthreads();
        {
            unsigned long long ar = 0ull, az = 0ull, ai = 0ull, ah = 0ull;
            const unsigned long long* wr2 = (const unsigned long long*)(w1s + (0 * 4 + jj) * 512 + kh * 256);
            const unsigned long long* wz2 = (const unsigned long long*)(w1s + (4 + jj) * 512 + kh * 256);
            const unsigned long long* wi2 = (const unsigned long long*)(w1s + (8 + jj) * 512 + kh * 256);
            const unsigned long long* wh2 = (const unsigned long long*)(w1s + (12 + jj) * 512 + kh * 256);
            const unsigned long long* hp  = (const unsigned long long*)hs + (size_t)kh * 128 * 32 + b;
#pragma unroll 8
            for (int k2 = 0; k2 < 128; k2++) {
                unsigned long long hv = hp[(size_t)k2 * 32];
                FMA2(ar, hv, wr2[k2], ar);
                FMA2(az, hv, wz2[k2], az);
                FMA2(ai, hv, wi2[k2], ai);
                FMA2(ah, hv, wh2[k2], ah);
            }
            if (kh) {
                *(unsigned long long*)&red[((0 * 4 + jj) * 32 + b) * 2]  = ar;
                *(unsigned long long*)&red[((4 + jj) * 32 + b) * 2]      = az;
                *(unsigned long long*)&red[((8 + jj) * 32 + b) * 2]      = ai;
                *(unsigned long long*)&red[((12 + jj) * 32 + b) * 2]     = ah;
            }
            __syncthreads();
            if (!kh) {
                float x0, x1;
                float sr, sz, si, sh;
                UNPACK2(x0, x1, ar); { float2 rv = *(float2*)&red[((0 * 4 + jj) * 32 + b) * 2]; sr = x0 + x1 + rv.x + rv.y; }
                UNPACK2(x0, x1, az); { float2 rv = *(float2*)&red[((4 + jj) * 32 + b) * 2];     sz = x0 + x1 + rv.x + rv.y; }
                UNPACK2(x0, x1, ai); { float2 rv = *(float2*)&red[((8 + jj) * 32 + b) * 2];     si = x0 + x1 + rv.x + rv.y; }
                UNPACK2(x0, x1, ah); { float2 rv = *(float2*)&red[((12 + jj) * 32 + b) * 2];    sh = x0 + x1 + rv.x + rv.y; }
                float rg = sigmoidf_(sr + b1r);
                float zg = sigmoidf_(sz + b1z);
                float ng = tanhf((si + bi1n) + rg * (sh + bh1n));
                float h1v = hs[hidx];
                float h2 = (1.f - zg) * ng + zg * h1v;
                g_h[hidx] = h2;
                g_outsT[(size_t)j * NROW + (size_t)t * 32 + b] = h2;
            }
        }
        target += RNC; gbarrier(target);
    }
}

// ---------------- launch ----------------
extern "C" void kernel_launch(void* const* d_in, const int* in_sizes, int n_in,
                              void* d_out, int out_size)
{
    const int*   x    = (const int*)d_in[0];
    const float* emb  = (const float*)d_in[1];
    const float* Wih  = (const float*)d_in[2];   // [2][1536][512]
    const float* Whh  = (const float*)d_in[3];
    const float* bih  = (const float*)d_in[4];   // [2][1536]
    const float* bhh  = (const float*)d_in[5];
    const float* Wout = (const float*)d_in[6];   // [32000][512]
    const float* bout = (const float*)d_in[7];
    float* out = (float*)d_out;

    const size_t L1W = (size_t)G3 * HH;
    const size_t NOFF = L1W + (size_t)1024 * HH;

    prep_kernel<<<256, 256>>>(Wih + L1W, Whh + L1W, bih + G3, bhh + G3);

    float* gi0T;  cudaGetSymbolAddress((void**)&gi0T,  g_gi0T);
    float* outsT; cudaGetSymbolAddress((void**)&outsT, g_outsT);

    gemm_f32<false, true, true, false><<<dim3(NROW / 128, G3 / 128), 256>>>(
        Wih, nullptr, bih, gi0T, G3, NROW, HH, x, emb);

    cudaFuncSetAttribute(recurrent_kernel,
                         cudaFuncAttributeMaxDynamicSharedMemorySize, SMEM_FLOATS * 4);
    recurrent_kernel<<<RNC, 256, SMEM_FLOATS * 4>>>(
        Whh, bhh, Wih + NOFF, bih + G3 + 1024, Whh + NOFF, bhh + G3 + 1024);

    cudaFuncSetAttribute(gemm2_bf16,
                         cudaFuncAttributeMaxDynamicSharedMemorySize, G2_SMEM);
    gemm2_bf16<<<dim3(VV / 128, NROW / 128), 256, G2_SMEM>>>(outsT, Wout, bout, out);
}